// round 14
// baseline (speedup 1.0000x reference)
#include <cuda_runtime.h>
#include <cuda_bf16.h>
#include <math.h>
#include <stdint.h>

// Problem constants
#define BSZ  128
#define TLEN 512
// H1=256, H2=128, H3=64

// ---------------------------------------------------------------------------
// Static device scratch (no runtime allocation).
// ---------------------------------------------------------------------------
__device__ float         g_xg[(size_t)BSZ * TLEN * 768];
__device__ __nv_bfloat16 g_xh[(size_t)BSZ * TLEN * 256];
__device__ __nv_bfloat16 g_xl[(size_t)BSZ * TLEN * 256];
__device__ __nv_bfloat16 g_wth[221184];
__device__ __nv_bfloat16 g_wtl[221184];
__device__ float         g_hA[BSZ * 64];

typedef unsigned long long ull;

__device__ __forceinline__ float sigf(float x) {
    return __fdividef(1.0f, 1.0f + __expf(-x));
}

__device__ __forceinline__ uint32_t smem_u32(const void* p) {
    uint32_t a;
    asm("{ .reg .u64 t; cvta.to.shared.u64 t, %1; cvt.u32.u64 %0, t; }"
        : "=r"(a) : "l"(p));
    return a;
}

__device__ __forceinline__ void st_cluster_f32(uint32_t laddr, uint32_t rank, float v) {
    uint32_t r;
    asm volatile("mapa.shared::cluster.u32 %0, %1, %2;" : "=r"(r) : "r"(laddr), "r"(rank));
    asm volatile("st.shared::cluster.b32 [%0], %1;" :: "r"(r), "r"(__float_as_uint(v)) : "memory");
}

#define CLUSTER_SYNC_ASM() do {                                          \
    asm volatile("barrier.cluster.arrive.aligned;" ::: "memory");        \
    asm volatile("barrier.cluster.wait.aligned;"   ::: "memory");        \
} while (0)

// Packed dual-fp32 FMA (Blackwell f32x2 pipe): acc += a * b elementwise.
#define FMA_X2(acc, a, b) \
    asm("fma.rn.f32x2 %0, %1, %2, %0;" : "+l"(acc) : "l"(a), "l"(b))

__device__ __forceinline__ ull packf2(float lo, float hi) {
    return (ull)__float_as_uint(lo) | ((ull)__float_as_uint(hi) << 32);
}
__device__ __forceinline__ float sumf2(ull v) {
    return __uint_as_float((uint32_t)v) + __uint_as_float((uint32_t)(v >> 32));
}

// bf16 hi/lo split of an fp32 value
__device__ __forceinline__ void bf16_split(float a, __nv_bfloat16& hi, __nv_bfloat16& lo) {
    hi = __float2bfloat16_rn(a);
    lo = __float2bfloat16_rn(a - __bfloat162float(hi));
}

// m16n8k16 bf16 MMA, fp32 accumulate
#define MMA_BF16(c, a, b)                                                       \
    asm volatile(                                                               \
        "mma.sync.aligned.m16n8k16.row.col.f32.bf16.bf16.f32 "                  \
        "{%0,%1,%2,%3}, {%4,%5,%6,%7}, {%8,%9}, {%0,%1,%2,%3};"                 \
        : "+f"((c)[0]), "+f"((c)[1]), "+f"((c)[2]), "+f"((c)[3])                \
        : "r"((a)[0]), "r"((a)[1]), "r"((a)[2]), "r"((a)[3]),                   \
          "r"((b)[0]), "r"((b)[1]))

// ---------------------------------------------------------------------------
// Weight transpose + bf16 hi/lo split:  W [K,N] fp32 -> WT_hi/WT_lo [N,K] bf16
// ---------------------------------------------------------------------------
__global__ void wsplit_kernel(const float* __restrict__ W, int K, int N, int off)
{
    int idx = blockIdx.x * 256 + threadIdx.x;
    if (idx < K * N) {
        int k = idx / N, n = idx % N;
        __nv_bfloat16 hi, lo;
        bf16_split(W[idx], hi, lo);
        g_wth[off + (size_t)n * K + k] = hi;
        g_wtl[off + (size_t)n * K + k] = lo;
    }
}

// ---------------------------------------------------------------------------
// X split: fp32 [n] -> g_xh/g_xl bf16 (used once, for `text`)
// ---------------------------------------------------------------------------
__global__ void xsplit_kernel(const float* __restrict__ X, int n)
{
    int idx = blockIdx.x * 256 + threadIdx.x;
    if (idx < n) {
        __nv_bfloat16 hi, lo;
        bf16_split(X[idx], hi, lo);
        g_xh[idx] = hi;
        g_xl[idx] = lo;
    }
}

// ---------------------------------------------------------------------------
// bf16x3 tensor-core GEMM with bias (unchanged).
// ---------------------------------------------------------------------------
__global__ void __launch_bounds__(256, 2)
gemm_mma_kernel(const float* __restrict__ bias, int K, int Ntot, int wt_off)
{
    __shared__ __nv_bfloat16 Ah[128 * 40], Al[128 * 40];
    __shared__ __nv_bfloat16 Bh[64 * 40],  Bl[64 * 40];

    const int tid  = threadIdx.x;
    const int wid  = tid >> 5;
    const int lane = tid & 31;
    const int wm   = wid & 3;
    const int wn   = wid >> 2;
    const int m0   = blockIdx.y * 128;
    const int n0   = blockIdx.x * 64;
    const int g    = lane >> 2;
    const int tg   = lane & 3;

    const __nv_bfloat16* wth = g_wth + wt_off;
    const __nv_bfloat16* wtl = g_wtl + wt_off;

    float c[2][4][4];
#pragma unroll
    for (int mt = 0; mt < 2; mt++)
#pragma unroll
        for (int nt = 0; nt < 4; nt++)
#pragma unroll
            for (int i = 0; i < 4; i++) c[mt][nt][i] = 0.0f;

    for (int k0 = 0; k0 < K; k0 += 32) {
#pragma unroll
        for (int it = tid; it < 512; it += 256) {
            int r = it >> 2, q = it & 3;
            size_t go = (size_t)(m0 + r) * K + k0 + q * 8;
            *(uint4*)&Ah[r * 40 + q * 8] = *(const uint4*)&g_xh[go];
            *(uint4*)&Al[r * 40 + q * 8] = *(const uint4*)&g_xl[go];
        }
        {
            int r = tid >> 2, q = tid & 3;
            size_t go = (size_t)(n0 + r) * K + k0 + q * 8;
            *(uint4*)&Bh[r * 40 + q * 8] = *(const uint4*)&wth[go];
            *(uint4*)&Bl[r * 40 + q * 8] = *(const uint4*)&wtl[go];
        }
        __syncthreads();

#pragma unroll
        for (int ks = 0; ks < 2; ks++) {
            uint32_t ah[2][4], al[2][4], bh[4][2], bl[4][2];
            const int cb = ks * 16 + tg * 2;
#pragma unroll
            for (int mt = 0; mt < 2; mt++) {
                int r0 = wm * 32 + mt * 16 + g;
                ah[mt][0] = *(const uint32_t*)&Ah[(r0    ) * 40 + cb];
                ah[mt][1] = *(const uint32_t*)&Ah[(r0 + 8) * 40 + cb];
                ah[mt][2] = *(const uint32_t*)&Ah[(r0    ) * 40 + cb + 8];
                ah[mt][3] = *(const uint32_t*)&Ah[(r0 + 8) * 40 + cb + 8];
                al[mt][0] = *(const uint32_t*)&Al[(r0    ) * 40 + cb];
                al[mt][1] = *(const uint32_t*)&Al[(r0 + 8) * 40 + cb];
                al[mt][2] = *(const uint32_t*)&Al[(r0    ) * 40 + cb + 8];
                al[mt][3] = *(const uint32_t*)&Al[(r0 + 8) * 40 + cb + 8];
            }
#pragma unroll
            for (int nt = 0; nt < 4; nt++) {
                int rn = wn * 32 + nt * 8 + g;
                bh[nt][0] = *(const uint32_t*)&Bh[rn * 40 + cb];
                bh[nt][1] = *(const uint32_t*)&Bh[rn * 40 + cb + 8];
                bl[nt][0] = *(const uint32_t*)&Bl[rn * 40 + cb];
                bl[nt][1] = *(const uint32_t*)&Bl[rn * 40 + cb + 8];
            }
#pragma unroll
            for (int mt = 0; mt < 2; mt++)
#pragma unroll
                for (int nt = 0; nt < 4; nt++) {
                    MMA_BF16(c[mt][nt], ah[mt], bh[nt]);
                    MMA_BF16(c[mt][nt], ah[mt], bl[nt]);
                    MMA_BF16(c[mt][nt], al[mt], bh[nt]);
                }
        }
        __syncthreads();
    }

#pragma unroll
    for (int mt = 0; mt < 2; mt++)
#pragma unroll
        for (int nt = 0; nt < 4; nt++) {
            int row = m0 + wm * 32 + mt * 16 + g;
            int col = n0 + wn * 32 + nt * 8 + tg * 2;
            float b0 = bias[col], b1 = bias[col + 1];
            float2 o0 = make_float2(c[mt][nt][0] + b0, c[mt][nt][1] + b1);
            float2 o1 = make_float2(c[mt][nt][2] + b0, c[mt][nt][3] + b1);
            *(float2*)&g_xg[(size_t)row * Ntot + col]       = o0;
            *(float2*)&g_xg[(size_t)(row + 8) * Ntot + col] = o1;
        }
}

// ---------------------------------------------------------------------------
// Persistent GRU layers 2/3: U register-cached + packed f32x2 FMA (unchanged).
// ---------------------------------------------------------------------------
template <int H, int UREG, bool RELU, bool WSEQ>
__global__ void __launch_bounds__(3 * H, 1)
gru_layer_reg_kernel(const float* __restrict__ U,
                     const float* __restrict__ brec)
{
    constexpr int NC  = 3 * H;
    constexpr int KS  = H - UREG;
    constexpr int KSp = (KS > 0) ? KS + 4 : 4;

    extern __shared__ float smem[];
    float* UsT  = smem;
    float* hs   = UsT + (KS > 0 ? NC * KSp : 0);
    float* pres = hs + H;
    float* xsm  = pres + NC;

    const int b = blockIdx.x;
    const int c = threadIdx.x;

    ull upk[UREG / 2];
#pragma unroll
    for (int jp = 0; jp < UREG / 2; jp++) {
        float f0 = U[(size_t)(2 * jp)     * NC + c];
        float f1 = U[(size_t)(2 * jp + 1) * NC + c];
        upk[jp] = packf2(f0, f1);
    }
    if constexpr (KS > 0) {
        for (int k = 0; k < KS; k++)
            UsT[c * KSp + k] = U[(size_t)(UREG + k) * NC + c];
    }

    if (c < H) hs[c] = 0.0f;
    const float br = brec[c];
    __syncthreads();

    const float* xgb = &g_xg[(size_t)b * TLEN * NC + c];

    float xv = xgb[0];
    for (int t = 0; t < TLEN; t++) {
        float xn = xgb[(size_t)(t + 1 < TLEN ? t + 1 : t) * NC];

        ull accA = 0ull, accB = 0ull;
#pragma unroll
        for (int kq = 0; kq < UREG / 4; kq++) {
            ulonglong2 hv = *(const ulonglong2*)&hs[kq * 4];
            FMA_X2(accA, upk[2 * kq],     hv.x);
            FMA_X2(accB, upk[2 * kq + 1], hv.y);
        }
        if constexpr (KS > 0) {
#pragma unroll
            for (int jq = 0; jq < KS / 4; jq++) {
                ulonglong2 uv = *(const ulonglong2*)&UsT[c * KSp + jq * 4];
                ulonglong2 hv = *(const ulonglong2*)&hs[UREG + jq * 4];
                FMA_X2(accA, uv.x, hv.x);
                FMA_X2(accB, uv.y, hv.y);
            }
        }
        pres[c] = sumf2(accA) + sumf2(accB) + br;
        xsm[c]  = xv;
        __syncthreads();

        if (c < H) {
            float z = sigf(xsm[c] + pres[c]);
            float r = sigf(xsm[H + c] + pres[H + c]);
            float cand = xsm[2 * H + c] + r * pres[2 * H + c];
            float hh = RELU ? fmaxf(cand, 0.0f) : sigf(cand);
            float hn = z * hs[c] + (1.0f - z) * hh;
            hs[c] = hn;
            if (WSEQ) {
                size_t sidx = ((size_t)b * TLEN + t) * H + c;
                __nv_bfloat16 hi, lo;
                bf16_split(hn, hi, lo);
                g_xh[sidx] = hi;
                g_xl[sidx] = lo;
            } else if (t == TLEN - 1) {
                g_hA[b * H + c] = hn;
            }
        }
        __syncthreads();
        xv = xn;
    }
}

// ---------------------------------------------------------------------------
// Persistent GRU layer 1 (H=256), 4-CTA cluster, 768 threads/CTA (24 warps).
// 4-way k-split: quarter q = t/192 owns k in [q*64, (q+1)*64) — the whole
// per-thread U slice lives in 32 packed-f32x2 registers. Per-step cluster
// sync via barrier.cluster (R13's mbarrier protocol was slower: arrives
// serialize on the barrier word).
// ---------------------------------------------------------------------------
__global__ void __cluster_dims__(4, 1, 1) __launch_bounds__(768, 1)
gru_layer1_kernel(const float* __restrict__ U,
                  const float* __restrict__ brec)
{
    constexpr int H = 256, NC3 = 768;
    constexpr int NB = 4;              // batches per cluster
    constexpr int UR = 64;             // k per thread, all in registers

    extern __shared__ float smem[];
    float* hsb  = smem;                 // [2][NB][256] double-buffered h (2048)
    float* part = hsb + 2048;           // [4][192][4] partial sums (3072)
    float* xsm  = part + 3072;          // [192][4] xg staging (768)

    const int t = threadIdx.x;          // 0..767
    const int q = t / 192;              // k-quarter
    const int c = t % 192;              // gate column within CTA slice
    uint32_t rank;
    asm("mov.u32 %0, %%cluster_ctarank;" : "=r"(rank));
    const int bgrp = blockIdx.y;

    const int gg = c >> 6, il = c & 63;
    const int gc = gg * H + (int)rank * 64 + il;   // global gate column
    const int kbase = q * UR;

    // U slice: 64 k-values in 32 packed-f32x2 registers.
    ull upk[UR / 2];
#pragma unroll
    for (int jp = 0; jp < UR / 2; jp++) {
        float f0 = U[(size_t)(kbase + 2 * jp)     * NC3 + gc];
        float f1 = U[(size_t)(kbase + 2 * jp + 1) * NC3 + gc];
        upk[jp] = packf2(f0, f1);
    }

    for (int idx = t; idx < 2 * NB * H; idx += 768) hsb[idx] = 0.0f;

    const float br = brec[gc];
    const uint32_t hsb_u32 = smem_u32(hsb);

    __syncthreads();
    CLUSTER_SYNC_ASM();                 // h zeros visible cluster-wide

    // prefetch xg for t=0 (quarter-0 threads own xg staging)
    float xv[NB];
    if (q == 0) {
#pragma unroll
        for (int bs = 0; bs < NB; bs++)
            xv[bs] = g_xg[((size_t)(bgrp * NB + bs) * TLEN + 0) * NC3 + gc];
    }

    for (int step = 0; step < TLEN; step++) {
        const int cur = step & 1;
        const int nxt = cur ^ 1;
        const float* hc = hsb + cur * (NB * H);
        const int tn = (step + 1 < TLEN) ? step + 1 : step;

        float xn[NB];
        if (q == 0) {
#pragma unroll
            for (int bs = 0; bs < NB; bs++)
                xn[bs] = g_xg[((size_t)(bgrp * NB + bs) * TLEN + tn) * NC3 + gc];
        }

        ull accA[NB], accB[NB];
#pragma unroll
        for (int bs = 0; bs < NB; bs++) { accA[bs] = 0ull; accB[bs] = 0ull; }

#pragma unroll
        for (int kq = 0; kq < UR / 4; kq++) {
#pragma unroll
            for (int bs = 0; bs < NB; bs++) {
                ulonglong2 hv = *(const ulonglong2*)&hc[bs * H + kbase + kq * 4];
                FMA_X2(accA[bs], upk[2 * kq],     hv.x);
                FMA_X2(accB[bs], upk[2 * kq + 1], hv.y);
            }
        }

        float4 ps;
        ps.x = sumf2(accA[0]) + sumf2(accB[0]);
        ps.y = sumf2(accA[1]) + sumf2(accB[1]);
        ps.z = sumf2(accA[2]) + sumf2(accB[2]);
        ps.w = sumf2(accA[3]) + sumf2(accB[3]);
        if (q == 0) {
            ps.x += br; ps.y += br; ps.z += br; ps.w += br;
            *(float4*)&xsm[c * 4] = make_float4(xv[0], xv[1], xv[2], xv[3]);
        }
        *(float4*)&part[(q * 192 + c) * 4] = ps;
        __syncthreads();

        // gate combine + DSMEM broadcast: items (bs, j) over threads < 256
        if (t < 256) {
            const int bs = t >> 6, j = t & 63;
            const int jz = j, jr = 64 + j, jh = 128 + j;
            float pz = part[jz * 4 + bs]        + part[(192 + jz) * 4 + bs]
                     + part[(384 + jz) * 4 + bs] + part[(576 + jz) * 4 + bs];
            float pr = part[jr * 4 + bs]        + part[(192 + jr) * 4 + bs]
                     + part[(384 + jr) * 4 + bs] + part[(576 + jr) * 4 + bs];
            float ph = part[jh * 4 + bs]        + part[(192 + jh) * 4 + bs]
                     + part[(384 + jh) * 4 + bs] + part[(576 + jh) * 4 + bs];
            float z = sigf(xsm[jz * 4 + bs] + pz);
            float r = sigf(xsm[jr * 4 + bs] + pr);
            float cand = xsm[jh * 4 + bs] + r * ph;
            float hh = sigf(cand);
            float hold = hc[bs * H + (int)rank * 64 + j];
            float hn = z * hold + (1.0f - z) * hh;

            int b = bgrp * NB + bs;
            size_t sidx = ((size_t)b * TLEN + step) * H + rank * 64 + j;
            __nv_bfloat16 hi, lo;
            bf16_split(hn, hi, lo);
            g_xh[sidx] = hi;
            g_xl[sidx] = lo;

            uint32_t dst = hsb_u32 +
                (uint32_t)((nxt * (NB * H) + bs * H + (int)rank * 64 + j) * 4);
#pragma unroll
            for (uint32_t rr = 0; rr < 4; rr++) st_cluster_f32(dst, rr, hn);
        }
        CLUSTER_SYNC_ASM();

        if (q == 0) {
#pragma unroll
            for (int bs = 0; bs < NB; bs++) xv[bs] = xn[bs];
        }
    }
}

// ---------------------------------------------------------------------------
// Output head: out[b] = sigmoid(h3[b,:] . Wo + bo)
// ---------------------------------------------------------------------------
__global__ void head_kernel(const float* __restrict__ Wo,
                            const float* __restrict__ bo,
                            float* __restrict__ out)
{
    int b = threadIdx.x;
    if (b < BSZ) {
        float s = bo[0];
#pragma unroll
        for (int k = 0; k < 64; k++) s += g_hA[b * 64 + k] * Wo[k];
        out[b] = sigf(s);
    }
}

// ---------------------------------------------------------------------------
// kernel_launch. Inputs: text, W1, U1, b1, W2, U2, b2, W3, U3, b3, Wo, bo
// Launch order keeps gru_layer1_kernel 4th so ncu profiles it.
// ---------------------------------------------------------------------------
extern "C" void kernel_launch(void* const* d_in, const int* in_sizes, int n_in,
                              void* d_out, int out_size)
{
    (void)in_sizes; (void)n_in; (void)out_size;

    const float* text = (const float*)d_in[0];
    const float* W1   = (const float*)d_in[1];
    const float* U1   = (const float*)d_in[2];
    const float* b1   = (const float*)d_in[3];
    const float* W2   = (const float*)d_in[4];
    const float* U2   = (const float*)d_in[5];
    const float* b2   = (const float*)d_in[6];
    const float* W3   = (const float*)d_in[7];
    const float* U3   = (const float*)d_in[8];
    const float* b3   = (const float*)d_in[9];
    const float* Wo   = (const float*)d_in[10];
    const float* bo   = (const float*)d_in[11];
    float* out = (float*)d_out;

    const int M = BSZ * TLEN;                 // 65536

    // Dynamic smem (bytes)
    const size_t smem_l1 = (size_t)(2048 + 3072 + 768) * 4;   // 23552
    const size_t smem_l2 = (size_t)(384 * 36 + 128 + 384 + 384) * 4;
    const size_t smem_l3 = (size_t)(64 + 192 + 192) * 4;

    cudaFuncSetAttribute(gru_layer1_kernel,
                         cudaFuncAttributeMaxDynamicSharedMemorySize, (int)smem_l1);
    cudaFuncSetAttribute((const void*)gru_layer_reg_kernel<128, 96, false, true>,
                         cudaFuncAttributeMaxDynamicSharedMemorySize, (int)smem_l2);
    cudaFuncSetAttribute((const void*)gru_layer_reg_kernel<64, 64, true, false>,
                         cudaFuncAttributeMaxDynamicSharedMemorySize, (int)smem_l3);

    // ---- Layer 1: F=128 -> H=256 (gru_layer1 is the 4th launch for ncu) ----
    wsplit_kernel<<<(128 * 768 + 255) / 256, 256>>>(W1, 128, 768, 0);
    xsplit_kernel<<<(M * 128 + 255) / 256, 256>>>(text, M * 128);
    gemm_mma_kernel<<<dim3(768 / 64, M / 128), 256>>>(b1, 128, 768, 0);
    gru_layer1_kernel<<<dim3(4, 32), 768, smem_l1>>>(U1, b1 + 768);

    // ---- Layer 2: H=256 -> H=128 ----
    wsplit_kernel<<<(256 * 384 + 255) / 256, 256>>>(W2, 256, 384, 98304);
    gemm_mma_kernel<<<dim3(384 / 64, M / 128), 256>>>(b2, 256, 384, 98304);
    gru_layer_reg_kernel<128, 96, false, true><<<BSZ, 384, smem_l2>>>(U2, b2 + 384);

    // ---- Layer 3: H=128 -> H=64 ----
    wsplit_kernel<<<(128 * 192 + 255) / 256, 256>>>(W3, 128, 192, 196608);
    gemm_mma_kernel<<<dim3(192 / 64, M / 128), 256>>>(b3, 128, 192, 196608);
    gru_layer_reg_kernel<64, 64, true, false><<<BSZ, 192, smem_l3>>>(U3, b3 + 192);

    // ---- Head ----
    head_kernel<<<1, 128>>>(Wo, bo, out);
}

// round 15
// speedup vs baseline: 1.0481x; 1.0481x over previous
#include <cuda_runtime.h>
#include <cuda_bf16.h>
#include <math.h>
#include <stdint.h>

// Problem constants
#define BSZ  128
#define TLEN 512
// H1=256, H2=128, H3=64

// ---------------------------------------------------------------------------
// Static device scratch (no runtime allocation).
// ---------------------------------------------------------------------------
__device__ float         g_xg[(size_t)BSZ * TLEN * 768];
__device__ __nv_bfloat16 g_xh[(size_t)BSZ * TLEN * 256];
__device__ __nv_bfloat16 g_xl[(size_t)BSZ * TLEN * 256];
__device__ __nv_bfloat16 g_wth[221184];
__device__ __nv_bfloat16 g_wtl[221184];
__device__ float         g_hA[BSZ * 64];

typedef unsigned long long ull;

__device__ __forceinline__ float sigf(float x) {
    return __fdividef(1.0f, 1.0f + __expf(-x));
}

__device__ __forceinline__ uint32_t smem_u32(const void* p) {
    uint32_t a;
    asm("{ .reg .u64 t; cvta.to.shared.u64 t, %1; cvt.u32.u64 %0, t; }"
        : "=r"(a) : "l"(p));
    return a;
}

__device__ __forceinline__ void st_cluster_f32(uint32_t laddr, uint32_t rank, float v) {
    uint32_t r;
    asm volatile("mapa.shared::cluster.u32 %0, %1, %2;" : "=r"(r) : "r"(laddr), "r"(rank));
    asm volatile("st.shared::cluster.b32 [%0], %1;" :: "r"(r), "r"(__float_as_uint(v)) : "memory");
}

#define CLUSTER_SYNC_ASM() do {                                          \
    asm volatile("barrier.cluster.arrive.aligned;" ::: "memory");        \
    asm volatile("barrier.cluster.wait.aligned;"   ::: "memory");        \
} while (0)

#define CLUSTER_ARRIVE() \
    asm volatile("barrier.cluster.arrive.aligned;" ::: "memory")
#define CLUSTER_WAIT() \
    asm volatile("barrier.cluster.wait.aligned;" ::: "memory")

// Packed dual-fp32 FMA (Blackwell f32x2 pipe): acc += a * b elementwise.
#define FMA_X2(acc, a, b) \
    asm("fma.rn.f32x2 %0, %1, %2, %0;" : "+l"(acc) : "l"(a), "l"(b))

__device__ __forceinline__ ull packf2(float lo, float hi) {
    return (ull)__float_as_uint(lo) | ((ull)__float_as_uint(hi) << 32);
}
__device__ __forceinline__ float sumf2(ull v) {
    return __uint_as_float((uint32_t)v) + __uint_as_float((uint32_t)(v >> 32));
}

// bf16 hi/lo split of an fp32 value
__device__ __forceinline__ void bf16_split(float a, __nv_bfloat16& hi, __nv_bfloat16& lo) {
    hi = __float2bfloat16_rn(a);
    lo = __float2bfloat16_rn(a - __bfloat162float(hi));
}

// m16n8k16 bf16 MMA, fp32 accumulate
#define MMA_BF16(c, a, b)                                                       \
    asm volatile(                                                               \
        "mma.sync.aligned.m16n8k16.row.col.f32.bf16.bf16.f32 "                  \
        "{%0,%1,%2,%3}, {%4,%5,%6,%7}, {%8,%9}, {%0,%1,%2,%3};"                 \
        : "+f"((c)[0]), "+f"((c)[1]), "+f"((c)[2]), "+f"((c)[3])                \
        : "r"((a)[0]), "r"((a)[1]), "r"((a)[2]), "r"((a)[3]),                   \
          "r"((b)[0]), "r"((b)[1]))

// ---------------------------------------------------------------------------
// Weight transpose + bf16 hi/lo split:  W [K,N] fp32 -> WT_hi/WT_lo [N,K] bf16
// ---------------------------------------------------------------------------
__global__ void wsplit_kernel(const float* __restrict__ W, int K, int N, int off)
{
    int idx = blockIdx.x * 256 + threadIdx.x;
    if (idx < K * N) {
        int k = idx / N, n = idx % N;
        __nv_bfloat16 hi, lo;
        bf16_split(W[idx], hi, lo);
        g_wth[off + (size_t)n * K + k] = hi;
        g_wtl[off + (size_t)n * K + k] = lo;
    }
}

// ---------------------------------------------------------------------------
// X split: fp32 [n] -> g_xh/g_xl bf16 (used once, for `text`)
// ---------------------------------------------------------------------------
__global__ void xsplit_kernel(const float* __restrict__ X, int n)
{
    int idx = blockIdx.x * 256 + threadIdx.x;
    if (idx < n) {
        __nv_bfloat16 hi, lo;
        bf16_split(X[idx], hi, lo);
        g_xh[idx] = hi;
        g_xl[idx] = lo;
    }
}

// ---------------------------------------------------------------------------
// bf16x3 tensor-core GEMM with bias (unchanged).
// ---------------------------------------------------------------------------
__global__ void __launch_bounds__(256, 2)
gemm_mma_kernel(const float* __restrict__ bias, int K, int Ntot, int wt_off)
{
    __shared__ __nv_bfloat16 Ah[128 * 40], Al[128 * 40];
    __shared__ __nv_bfloat16 Bh[64 * 40],  Bl[64 * 40];

    const int tid  = threadIdx.x;
    const int wid  = tid >> 5;
    const int lane = tid & 31;
    const int wm   = wid & 3;
    const int wn   = wid >> 2;
    const int m0   = blockIdx.y * 128;
    const int n0   = blockIdx.x * 64;
    const int g    = lane >> 2;
    const int tg   = lane & 3;

    const __nv_bfloat16* wth = g_wth + wt_off;
    const __nv_bfloat16* wtl = g_wtl + wt_off;

    float c[2][4][4];
#pragma unroll
    for (int mt = 0; mt < 2; mt++)
#pragma unroll
        for (int nt = 0; nt < 4; nt++)
#pragma unroll
            for (int i = 0; i < 4; i++) c[mt][nt][i] = 0.0f;

    for (int k0 = 0; k0 < K; k0 += 32) {
#pragma unroll
        for (int it = tid; it < 512; it += 256) {
            int r = it >> 2, q = it & 3;
            size_t go = (size_t)(m0 + r) * K + k0 + q * 8;
            *(uint4*)&Ah[r * 40 + q * 8] = *(const uint4*)&g_xh[go];
            *(uint4*)&Al[r * 40 + q * 8] = *(const uint4*)&g_xl[go];
        }
        {
            int r = tid >> 2, q = tid & 3;
            size_t go = (size_t)(n0 + r) * K + k0 + q * 8;
            *(uint4*)&Bh[r * 40 + q * 8] = *(const uint4*)&wth[go];
            *(uint4*)&Bl[r * 40 + q * 8] = *(const uint4*)&wtl[go];
        }
        __syncthreads();

#pragma unroll
        for (int ks = 0; ks < 2; ks++) {
            uint32_t ah[2][4], al[2][4], bh[4][2], bl[4][2];
            const int cb = ks * 16 + tg * 2;
#pragma unroll
            for (int mt = 0; mt < 2; mt++) {
                int r0 = wm * 32 + mt * 16 + g;
                ah[mt][0] = *(const uint32_t*)&Ah[(r0    ) * 40 + cb];
                ah[mt][1] = *(const uint32_t*)&Ah[(r0 + 8) * 40 + cb];
                ah[mt][2] = *(const uint32_t*)&Ah[(r0    ) * 40 + cb + 8];
                ah[mt][3] = *(const uint32_t*)&Ah[(r0 + 8) * 40 + cb + 8];
                al[mt][0] = *(const uint32_t*)&Al[(r0    ) * 40 + cb];
                al[mt][1] = *(const uint32_t*)&Al[(r0 + 8) * 40 + cb];
                al[mt][2] = *(const uint32_t*)&Al[(r0    ) * 40 + cb + 8];
                al[mt][3] = *(const uint32_t*)&Al[(r0 + 8) * 40 + cb + 8];
            }
#pragma unroll
            for (int nt = 0; nt < 4; nt++) {
                int rn = wn * 32 + nt * 8 + g;
                bh[nt][0] = *(const uint32_t*)&Bh[rn * 40 + cb];
                bh[nt][1] = *(const uint32_t*)&Bh[rn * 40 + cb + 8];
                bl[nt][0] = *(const uint32_t*)&Bl[rn * 40 + cb];
                bl[nt][1] = *(const uint32_t*)&Bl[rn * 40 + cb + 8];
            }
#pragma unroll
            for (int mt = 0; mt < 2; mt++)
#pragma unroll
                for (int nt = 0; nt < 4; nt++) {
                    MMA_BF16(c[mt][nt], ah[mt], bh[nt]);
                    MMA_BF16(c[mt][nt], ah[mt], bl[nt]);
                    MMA_BF16(c[mt][nt], al[mt], bh[nt]);
                }
        }
        __syncthreads();
    }

#pragma unroll
    for (int mt = 0; mt < 2; mt++)
#pragma unroll
        for (int nt = 0; nt < 4; nt++) {
            int row = m0 + wm * 32 + mt * 16 + g;
            int col = n0 + wn * 32 + nt * 8 + tg * 2;
            float b0 = bias[col], b1 = bias[col + 1];
            float2 o0 = make_float2(c[mt][nt][0] + b0, c[mt][nt][1] + b1);
            float2 o1 = make_float2(c[mt][nt][2] + b0, c[mt][nt][3] + b1);
            *(float2*)&g_xg[(size_t)row * Ntot + col]       = o0;
            *(float2*)&g_xg[(size_t)(row + 8) * Ntot + col] = o1;
        }
}

// ---------------------------------------------------------------------------
// Persistent GRU layers 2/3: U register-cached + packed f32x2 FMA (unchanged).
// ---------------------------------------------------------------------------
template <int H, int UREG, bool RELU, bool WSEQ>
__global__ void __launch_bounds__(3 * H, 1)
gru_layer_reg_kernel(const float* __restrict__ U,
                     const float* __restrict__ brec)
{
    constexpr int NC  = 3 * H;
    constexpr int KS  = H - UREG;
    constexpr int KSp = (KS > 0) ? KS + 4 : 4;

    extern __shared__ float smem[];
    float* UsT  = smem;
    float* hs   = UsT + (KS > 0 ? NC * KSp : 0);
    float* pres = hs + H;
    float* xsm  = pres + NC;

    const int b = blockIdx.x;
    const int c = threadIdx.x;

    ull upk[UREG / 2];
#pragma unroll
    for (int jp = 0; jp < UREG / 2; jp++) {
        float f0 = U[(size_t)(2 * jp)     * NC + c];
        float f1 = U[(size_t)(2 * jp + 1) * NC + c];
        upk[jp] = packf2(f0, f1);
    }
    if constexpr (KS > 0) {
        for (int k = 0; k < KS; k++)
            UsT[c * KSp + k] = U[(size_t)(UREG + k) * NC + c];
    }

    if (c < H) hs[c] = 0.0f;
    const float br = brec[c];
    __syncthreads();

    const float* xgb = &g_xg[(size_t)b * TLEN * NC + c];

    float xv = xgb[0];
    for (int t = 0; t < TLEN; t++) {
        float xn = xgb[(size_t)(t + 1 < TLEN ? t + 1 : t) * NC];

        ull accA = 0ull, accB = 0ull;
#pragma unroll
        for (int kq = 0; kq < UREG / 4; kq++) {
            ulonglong2 hv = *(const ulonglong2*)&hs[kq * 4];
            FMA_X2(accA, upk[2 * kq],     hv.x);
            FMA_X2(accB, upk[2 * kq + 1], hv.y);
        }
        if constexpr (KS > 0) {
#pragma unroll
            for (int jq = 0; jq < KS / 4; jq++) {
                ulonglong2 uv = *(const ulonglong2*)&UsT[c * KSp + jq * 4];
                ulonglong2 hv = *(const ulonglong2*)&hs[UREG + jq * 4];
                FMA_X2(accA, uv.x, hv.x);
                FMA_X2(accB, uv.y, hv.y);
            }
        }
        pres[c] = sumf2(accA) + sumf2(accB) + br;
        xsm[c]  = xv;
        __syncthreads();

        if (c < H) {
            float z = sigf(xsm[c] + pres[c]);
            float r = sigf(xsm[H + c] + pres[H + c]);
            float cand = xsm[2 * H + c] + r * pres[2 * H + c];
            float hh = RELU ? fmaxf(cand, 0.0f) : sigf(cand);
            float hn = z * hs[c] + (1.0f - z) * hh;
            hs[c] = hn;
            if (WSEQ) {
                size_t sidx = ((size_t)b * TLEN + t) * H + c;
                __nv_bfloat16 hi, lo;
                bf16_split(hn, hi, lo);
                g_xh[sidx] = hi;
                g_xl[sidx] = lo;
            } else if (t == TLEN - 1) {
                g_hA[b * H + c] = hn;
            }
        }
        __syncthreads();
        xv = xn;
    }
}

// ---------------------------------------------------------------------------
// Persistent GRU layer 1 (H=256), 4-CTA cluster, 384 threads/CTA (R11 shape).
// NEW: the 4 batches per cluster are split into 2 independent groups of 2,
// software-pipelined through the SPLIT cluster barrier: while group g's
// h-broadcast drains (arrive ... wait), the CTA computes the other group's
// dot+combine. Schedule per step: W0; wait; arrive; W1; wait; arrive
// (one dummy arrive in the prologue, one final wait in the epilogue).
// ---------------------------------------------------------------------------
__global__ void __cluster_dims__(4, 1, 1) __launch_bounds__(384, 1)
gru_layer1_kernel(const float* __restrict__ U,
                  const float* __restrict__ brec)
{
    constexpr int H = 256, NC3 = 768;
    constexpr int NG = 2;              // batch groups (pipelined)
    constexpr int NB = 2;              // batches per group
    constexpr int UR = 96;             // k in registers per thread
    constexpr int KT = 32;             // k tail in smem per thread

    extern __shared__ float smem[];
    float* hsb  = smem;                 // [NG][2][NB][H]  = 2048 floats
    float* Ut   = hsb + 2048;           // [8][384][4]     = 12288
    float* part = Ut + 12288;           // [NG][2][192][NB]= 1536
    float* xsm  = part + 1536;          // [NG][192][NB]   = 768

    const int t    = threadIdx.x;
    const int half = (t >= 192) ? 1 : 0;      // k-half: warps 0-5 / 6-11
    const int c    = t - half * 192;
    uint32_t rank;
    asm("mov.u32 %0, %%cluster_ctarank;" : "=r"(rank));
    const int bgrp = blockIdx.y;

    const int gg = c >> 6, il = c & 63;
    const int gc = gg * H + (int)rank * 64 + il;   // global gate column
    const int kbase = half * 128;

    // U registers (packed pairs) + smem tail (R11 layout)
    ull upk[UR / 2];
#pragma unroll
    for (int jp = 0; jp < UR / 2; jp++) {
        float f0 = U[(size_t)(kbase + 2 * jp)     * NC3 + gc];
        float f1 = U[(size_t)(kbase + 2 * jp + 1) * NC3 + gc];
        upk[jp] = packf2(f0, f1);
    }
    for (int j = 0; j < KT; j++)
        Ut[((j >> 2) * 384 + t) * 4 + (j & 3)] = U[(size_t)(kbase + UR + j) * NC3 + gc];

    for (int idx = t; idx < 2048; idx += 384) hsb[idx] = 0.0f;

    const float br = brec[gc];
    const uint32_t hsb_u32 = smem_u32(hsb);

    __syncthreads();
    CLUSTER_SYNC_ASM();                 // h zeros visible cluster-wide

    // prefetch xg for t=0 (half-0 threads own xg staging)
    float xv[NG][NB];
    if (half == 0) {
#pragma unroll
        for (int g = 0; g < NG; g++)
#pragma unroll
            for (int bs = 0; bs < NB; bs++)
                xv[g][bs] = g_xg[((size_t)(bgrp * 4 + g * 2 + bs) * TLEN + 0) * NC3 + gc];
    }

    CLUSTER_ARRIVE();                   // dummy generation (prologue)

    for (int step = 0; step < TLEN; step++) {
        const int cur = step & 1;
        const int nxt = cur ^ 1;
        const int tn = (step + 1 < TLEN) ? step + 1 : step;

#pragma unroll
        for (int g = 0; g < NG; g++) {
            float* hg    = hsb + g * (2 * NB * H);
            const float* hcg = hg + cur * (NB * H);
            float* partg = part + g * (2 * 192 * NB);
            float* xsmg  = xsm + g * (192 * NB);

            float xn[NB];
            if (half == 0) {
#pragma unroll
                for (int bs = 0; bs < NB; bs++)
                    xn[bs] = g_xg[((size_t)(bgrp * 4 + g * 2 + bs) * TLEN + tn) * NC3 + gc];
            }

            ull accA[NB], accB[NB];
#pragma unroll
            for (int bs = 0; bs < NB; bs++) { accA[bs] = 0ull; accB[bs] = 0ull; }

            // main: 96 k from registers, h broadcast from smem
#pragma unroll
            for (int kq = 0; kq < UR / 4; kq++) {
#pragma unroll
                for (int bs = 0; bs < NB; bs++) {
                    ulonglong2 hv = *(const ulonglong2*)&hcg[bs * H + kbase + kq * 4];
                    FMA_X2(accA[bs], upk[2 * kq],     hv.x);
                    FMA_X2(accB[bs], upk[2 * kq + 1], hv.y);
                }
            }
            // tail: 32 k from smem
#pragma unroll
            for (int jq = 0; jq < KT / 4; jq++) {
                ulonglong2 uv = *(const ulonglong2*)&Ut[(jq * 384 + t) * 4];
#pragma unroll
                for (int bs = 0; bs < NB; bs++) {
                    ulonglong2 hv = *(const ulonglong2*)&hcg[bs * H + kbase + UR + jq * 4];
                    FMA_X2(accA[bs], uv.x, hv.x);
                    FMA_X2(accB[bs], uv.y, hv.y);
                }
            }

            float2 ps;
            ps.x = sumf2(accA[0]) + sumf2(accB[0]);
            ps.y = sumf2(accA[1]) + sumf2(accB[1]);
            if (half == 0) {
                ps.x += br; ps.y += br;
                *(float2*)&xsmg[c * NB] = make_float2(xv[g][0], xv[g][1]);
            }
            *(float2*)&partg[(half * 192 + c) * NB] = ps;
            __syncthreads();

            // gate combine + DSMEM broadcast: items (bs, j), threads < 128
            if (t < NB * 64) {
                const int bs = t >> 6, j = t & 63;
                const int jz = j, jr = 64 + j, jh = 128 + j;
                float pz = partg[jz * NB + bs] + partg[(192 + jz) * NB + bs];
                float pr = partg[jr * NB + bs] + partg[(192 + jr) * NB + bs];
                float ph = partg[jh * NB + bs] + partg[(192 + jh) * NB + bs];
                float z = sigf(xsmg[jz * NB + bs] + pz);
                float r = sigf(xsmg[jr * NB + bs] + pr);
                float cand = xsmg[jh * NB + bs] + r * ph;
                float hh = sigf(cand);
                float hold = hcg[bs * H + (int)rank * 64 + j];
                float hn = z * hold + (1.0f - z) * hh;

                int b = bgrp * 4 + g * 2 + bs;
                size_t sidx = ((size_t)b * TLEN + step) * H + rank * 64 + j;
                __nv_bfloat16 hi, lo;
                bf16_split(hn, hi, lo);
                g_xh[sidx] = hi;
                g_xl[sidx] = lo;

                uint32_t dst = hsb_u32 +
                    (uint32_t)((g * (2 * NB * H) + nxt * (NB * H) +
                                bs * H + (int)rank * 64 + j) * 4);
#pragma unroll
                for (uint32_t rr = 0; rr < 4; rr++) st_cluster_f32(dst, rr, hn);
            }

            // Close the previous generation (other group's stores become
            // visible) and open a new one covering THIS group's stores.
            CLUSTER_WAIT();
            CLUSTER_ARRIVE();

            if (half == 0) {
#pragma unroll
                for (int bs = 0; bs < NB; bs++) xv[g][bs] = xn[bs];
            }
        }
    }
    CLUSTER_WAIT();                     // drain final generation
}

// ---------------------------------------------------------------------------
// Output head: out[b] = sigmoid(h3[b,:] . Wo + bo)
// ---------------------------------------------------------------------------
__global__ void head_kernel(const float* __restrict__ Wo,
                            const float* __restrict__ bo,
                            float* __restrict__ out)
{
    int b = threadIdx.x;
    if (b < BSZ) {
        float s = bo[0];
#pragma unroll
        for (int k = 0; k < 64; k++) s += g_hA[b * 64 + k] * Wo[k];
        out[b] = sigf(s);
    }
}

// ---------------------------------------------------------------------------
// kernel_launch. Inputs: text, W1, U1, b1, W2, U2, b2, W3, U3, b3, Wo, bo
// Launch order keeps gru_layer1_kernel 4th so ncu profiles it.
// ---------------------------------------------------------------------------
extern "C" void kernel_launch(void* const* d_in, const int* in_sizes, int n_in,
                              void* d_out, int out_size)
{
    (void)in_sizes; (void)n_in; (void)out_size;

    const float* text = (const float*)d_in[0];
    const float* W1   = (const float*)d_in[1];
    const float* U1   = (const float*)d_in[2];
    const float* b1   = (const float*)d_in[3];
    const float* W2   = (const float*)d_in[4];
    const float* U2   = (const float*)d_in[5];
    const float* b2   = (const float*)d_in[6];
    const float* W3   = (const float*)d_in[7];
    const float* U3   = (const float*)d_in[8];
    const float* b3   = (const float*)d_in[9];
    const float* Wo   = (const float*)d_in[10];
    const float* bo   = (const float*)d_in[11];
    float* out = (float*)d_out;

    const int M = BSZ * TLEN;                 // 65536

    // Dynamic smem (bytes)
    const size_t smem_l1 = (size_t)(2048 + 12288 + 1536 + 768) * 4;   // 66560
    const size_t smem_l2 = (size_t)(384 * 36 + 128 + 384 + 384) * 4;
    const size_t smem_l3 = (size_t)(64 + 192 + 192) * 4;

    cudaFuncSetAttribute(gru_layer1_kernel,
                         cudaFuncAttributeMaxDynamicSharedMemorySize, (int)smem_l1);
    cudaFuncSetAttribute((const void*)gru_layer_reg_kernel<128, 96, false, true>,
                         cudaFuncAttributeMaxDynamicSharedMemorySize, (int)smem_l2);
    cudaFuncSetAttribute((const void*)gru_layer_reg_kernel<64, 64, true, false>,
                         cudaFuncAttributeMaxDynamicSharedMemorySize, (int)smem_l3);

    // ---- Layer 1: F=128 -> H=256 (gru_layer1 is the 4th launch for ncu) ----
    wsplit_kernel<<<(128 * 768 + 255) / 256, 256>>>(W1, 128, 768, 0);
    xsplit_kernel<<<(M * 128 + 255) / 256, 256>>>(text, M * 128);
    gemm_mma_kernel<<<dim3(768 / 64, M / 128), 256>>>(b1, 128, 768, 0);
    gru_layer1_kernel<<<dim3(4, 32), 384, smem_l1>>>(U1, b1 + 768);

    // ---- Layer 2: H=256 -> H=128 ----
    wsplit_kernel<<<(256 * 384 + 255) / 256, 256>>>(W2, 256, 384, 98304);
    gemm_mma_kernel<<<dim3(384 / 64, M / 128), 256>>>(b2, 256, 384, 98304);
    gru_layer_reg_kernel<128, 96, false, true><<<BSZ, 384, smem_l2>>>(U2, b2 + 384);

    // ---- Layer 3: H=128 -> H=64 ----
    wsplit_kernel<<<(128 * 192 + 255) / 256, 256>>>(W3, 128, 192, 196608);
    gemm_mma_kernel<<<dim3(192 / 64, M / 128), 256>>>(b3, 128, 192, 196608);
    gru_layer_reg_kernel<64, 64, true, false><<<BSZ, 192, smem_l3>>>(U3, b3 + 192);

    // ---- Head ----
    head_kernel<<<1, 128>>>(Wo, bo, out);
}

// round 16
// speedup vs baseline: 1.0845x; 1.0347x over previous
#include <cuda_runtime.h>
#include <cuda_bf16.h>
#include <math.h>
#include <stdint.h>

// Problem constants
#define BSZ  128
#define TLEN 512
// H1=256, H2=128, H3=64

// ---------------------------------------------------------------------------
// Static device scratch (no runtime allocation).
// ---------------------------------------------------------------------------
__device__ float         g_xg[(size_t)BSZ * TLEN * 768];
__device__ __nv_bfloat16 g_xh[(size_t)BSZ * TLEN * 256];
__device__ __nv_bfloat16 g_xl[(size_t)BSZ * TLEN * 256];
__device__ __nv_bfloat16 g_wth[221184];
__device__ __nv_bfloat16 g_wtl[221184];
__device__ float         g_hA[BSZ * 64];

typedef unsigned long long ull;

__device__ __forceinline__ float sigf(float x) {
    return __fdividef(1.0f, 1.0f + __expf(-x));
}

__device__ __forceinline__ uint32_t smem_u32(const void* p) {
    uint32_t a;
    asm("{ .reg .u64 t; cvta.to.shared.u64 t, %1; cvt.u32.u64 %0, t; }"
        : "=r"(a) : "l"(p));
    return a;
}

__device__ __forceinline__ void st_cluster_f32(uint32_t laddr, uint32_t rank, float v) {
    uint32_t r;
    asm volatile("mapa.shared::cluster.u32 %0, %1, %2;" : "=r"(r) : "r"(laddr), "r"(rank));
    asm volatile("st.shared::cluster.b32 [%0], %1;" :: "r"(r), "r"(__float_as_uint(v)) : "memory");
}

#define CLUSTER_SYNC_ASM() do {                                          \
    asm volatile("barrier.cluster.arrive.aligned;" ::: "memory");        \
    asm volatile("barrier.cluster.wait.aligned;"   ::: "memory");        \
} while (0)

// Packed dual-fp32 FMA (Blackwell f32x2 pipe): acc += a * b elementwise.
#define FMA_X2(acc, a, b) \
    asm("fma.rn.f32x2 %0, %1, %2, %0;" : "+l"(acc) : "l"(a), "l"(b))

__device__ __forceinline__ ull packf2(float lo, float hi) {
    return (ull)__float_as_uint(lo) | ((ull)__float_as_uint(hi) << 32);
}
__device__ __forceinline__ float sumf2(ull v) {
    return __uint_as_float((uint32_t)v) + __uint_as_float((uint32_t)(v >> 32));
}

// bf16 hi/lo split of an fp32 value
__device__ __forceinline__ void bf16_split(float a, __nv_bfloat16& hi, __nv_bfloat16& lo) {
    hi = __float2bfloat16_rn(a);
    lo = __float2bfloat16_rn(a - __bfloat162float(hi));
}

// m16n8k16 bf16 MMA, fp32 accumulate
#define MMA_BF16(c, a, b)                                                       \
    asm volatile(                                                               \
        "mma.sync.aligned.m16n8k16.row.col.f32.bf16.bf16.f32 "                  \
        "{%0,%1,%2,%3}, {%4,%5,%6,%7}, {%8,%9}, {%0,%1,%2,%3};"                 \
        : "+f"((c)[0]), "+f"((c)[1]), "+f"((c)[2]), "+f"((c)[3])                \
        : "r"((a)[0]), "r"((a)[1]), "r"((a)[2]), "r"((a)[3]),                   \
          "r"((b)[0]), "r"((b)[1]))

// ---------------------------------------------------------------------------
// Weight transpose + bf16 hi/lo split:  W [K,N] fp32 -> WT_hi/WT_lo [N,K] bf16
// ---------------------------------------------------------------------------
__global__ void wsplit_kernel(const float* __restrict__ W, int K, int N, int off)
{
    int idx = blockIdx.x * 256 + threadIdx.x;
    if (idx < K * N) {
        int k = idx / N, n = idx % N;
        __nv_bfloat16 hi, lo;
        bf16_split(W[idx], hi, lo);
        g_wth[off + (size_t)n * K + k] = hi;
        g_wtl[off + (size_t)n * K + k] = lo;
    }
}

// ---------------------------------------------------------------------------
// X split: fp32 [n] -> g_xh/g_xl bf16 (used once, for `text`)
// ---------------------------------------------------------------------------
__global__ void xsplit_kernel(const float* __restrict__ X, int n)
{
    int idx = blockIdx.x * 256 + threadIdx.x;
    if (idx < n) {
        __nv_bfloat16 hi, lo;
        bf16_split(X[idx], hi, lo);
        g_xh[idx] = hi;
        g_xl[idx] = lo;
    }
}

// ---------------------------------------------------------------------------
// bf16x3 tensor-core GEMM with bias (unchanged).
// ---------------------------------------------------------------------------
__global__ void __launch_bounds__(256, 2)
gemm_mma_kernel(const float* __restrict__ bias, int K, int Ntot, int wt_off)
{
    __shared__ __nv_bfloat16 Ah[128 * 40], Al[128 * 40];
    __shared__ __nv_bfloat16 Bh[64 * 40],  Bl[64 * 40];

    const int tid  = threadIdx.x;
    const int wid  = tid >> 5;
    const int lane = tid & 31;
    const int wm   = wid & 3;
    const int wn   = wid >> 2;
    const int m0   = blockIdx.y * 128;
    const int n0   = blockIdx.x * 64;
    const int g    = lane >> 2;
    const int tg   = lane & 3;

    const __nv_bfloat16* wth = g_wth + wt_off;
    const __nv_bfloat16* wtl = g_wtl + wt_off;

    float c[2][4][4];
#pragma unroll
    for (int mt = 0; mt < 2; mt++)
#pragma unroll
        for (int nt = 0; nt < 4; nt++)
#pragma unroll
            for (int i = 0; i < 4; i++) c[mt][nt][i] = 0.0f;

    for (int k0 = 0; k0 < K; k0 += 32) {
#pragma unroll
        for (int it = tid; it < 512; it += 256) {
            int r = it >> 2, q = it & 3;
            size_t go = (size_t)(m0 + r) * K + k0 + q * 8;
            *(uint4*)&Ah[r * 40 + q * 8] = *(const uint4*)&g_xh[go];
            *(uint4*)&Al[r * 40 + q * 8] = *(const uint4*)&g_xl[go];
        }
        {
            int r = tid >> 2, q = tid & 3;
            size_t go = (size_t)(n0 + r) * K + k0 + q * 8;
            *(uint4*)&Bh[r * 40 + q * 8] = *(const uint4*)&wth[go];
            *(uint4*)&Bl[r * 40 + q * 8] = *(const uint4*)&wtl[go];
        }
        __syncthreads();

#pragma unroll
        for (int ks = 0; ks < 2; ks++) {
            uint32_t ah[2][4], al[2][4], bh[4][2], bl[4][2];
            const int cb = ks * 16 + tg * 2;
#pragma unroll
            for (int mt = 0; mt < 2; mt++) {
                int r0 = wm * 32 + mt * 16 + g;
                ah[mt][0] = *(const uint32_t*)&Ah[(r0    ) * 40 + cb];
                ah[mt][1] = *(const uint32_t*)&Ah[(r0 + 8) * 40 + cb];
                ah[mt][2] = *(const uint32_t*)&Ah[(r0    ) * 40 + cb + 8];
                ah[mt][3] = *(const uint32_t*)&Ah[(r0 + 8) * 40 + cb + 8];
                al[mt][0] = *(const uint32_t*)&Al[(r0    ) * 40 + cb];
                al[mt][1] = *(const uint32_t*)&Al[(r0 + 8) * 40 + cb];
                al[mt][2] = *(const uint32_t*)&Al[(r0    ) * 40 + cb + 8];
                al[mt][3] = *(const uint32_t*)&Al[(r0 + 8) * 40 + cb + 8];
            }
#pragma unroll
            for (int nt = 0; nt < 4; nt++) {
                int rn = wn * 32 + nt * 8 + g;
                bh[nt][0] = *(const uint32_t*)&Bh[rn * 40 + cb];
                bh[nt][1] = *(const uint32_t*)&Bh[rn * 40 + cb + 8];
                bl[nt][0] = *(const uint32_t*)&Bl[rn * 40 + cb];
                bl[nt][1] = *(const uint32_t*)&Bl[rn * 40 + cb + 8];
            }
#pragma unroll
            for (int mt = 0; mt < 2; mt++)
#pragma unroll
                for (int nt = 0; nt < 4; nt++) {
                    MMA_BF16(c[mt][nt], ah[mt], bh[nt]);
                    MMA_BF16(c[mt][nt], ah[mt], bl[nt]);
                    MMA_BF16(c[mt][nt], al[mt], bh[nt]);
                }
        }
        __syncthreads();
    }

#pragma unroll
    for (int mt = 0; mt < 2; mt++)
#pragma unroll
        for (int nt = 0; nt < 4; nt++) {
            int row = m0 + wm * 32 + mt * 16 + g;
            int col = n0 + wn * 32 + nt * 8 + tg * 2;
            float b0 = bias[col], b1 = bias[col + 1];
            float2 o0 = make_float2(c[mt][nt][0] + b0, c[mt][nt][1] + b1);
            float2 o1 = make_float2(c[mt][nt][2] + b0, c[mt][nt][3] + b1);
            *(float2*)&g_xg[(size_t)row * Ntot + col]       = o0;
            *(float2*)&g_xg[(size_t)(row + 8) * Ntot + col] = o1;
        }
}

// ---------------------------------------------------------------------------
// Persistent GRU layers 2/3: U register-cached + packed f32x2 FMA (unchanged).
// ---------------------------------------------------------------------------
template <int H, int UREG, bool RELU, bool WSEQ>
__global__ void __launch_bounds__(3 * H, 1)
gru_layer_reg_kernel(const float* __restrict__ U,
                     const float* __restrict__ brec)
{
    constexpr int NC  = 3 * H;
    constexpr int KS  = H - UREG;
    constexpr int KSp = (KS > 0) ? KS + 4 : 4;

    extern __shared__ float smem[];
    float* UsT  = smem;
    float* hs   = UsT + (KS > 0 ? NC * KSp : 0);
    float* pres = hs + H;
    float* xsm  = pres + NC;

    const int b = blockIdx.x;
    const int c = threadIdx.x;

    ull upk[UREG / 2];
#pragma unroll
    for (int jp = 0; jp < UREG / 2; jp++) {
        float f0 = U[(size_t)(2 * jp)     * NC + c];
        float f1 = U[(size_t)(2 * jp + 1) * NC + c];
        upk[jp] = packf2(f0, f1);
    }
    if constexpr (KS > 0) {
        for (int k = 0; k < KS; k++)
            UsT[c * KSp + k] = U[(size_t)(UREG + k) * NC + c];
    }

    if (c < H) hs[c] = 0.0f;
    const float br = brec[c];
    __syncthreads();

    const float* xgb = &g_xg[(size_t)b * TLEN * NC + c];

    float xv = xgb[0];
    for (int t = 0; t < TLEN; t++) {
        float xn = xgb[(size_t)(t + 1 < TLEN ? t + 1 : t) * NC];

        ull accA = 0ull, accB = 0ull;
#pragma unroll
        for (int kq = 0; kq < UREG / 4; kq++) {
            ulonglong2 hv = *(const ulonglong2*)&hs[kq * 4];
            FMA_X2(accA, upk[2 * kq],     hv.x);
            FMA_X2(accB, upk[2 * kq + 1], hv.y);
        }
        if constexpr (KS > 0) {
#pragma unroll
            for (int jq = 0; jq < KS / 4; jq++) {
                ulonglong2 uv = *(const ulonglong2*)&UsT[c * KSp + jq * 4];
                ulonglong2 hv = *(const ulonglong2*)&hs[UREG + jq * 4];
                FMA_X2(accA, uv.x, hv.x);
                FMA_X2(accB, uv.y, hv.y);
            }
        }
        pres[c] = sumf2(accA) + sumf2(accB) + br;
        xsm[c]  = xv;
        __syncthreads();

        if (c < H) {
            float z = sigf(xsm[c] + pres[c]);
            float r = sigf(xsm[H + c] + pres[H + c]);
            float cand = xsm[2 * H + c] + r * pres[2 * H + c];
            float hh = RELU ? fmaxf(cand, 0.0f) : sigf(cand);
            float hn = z * hs[c] + (1.0f - z) * hh;
            hs[c] = hn;
            if (WSEQ) {
                size_t sidx = ((size_t)b * TLEN + t) * H + c;
                __nv_bfloat16 hi, lo;
                bf16_split(hn, hi, lo);
                g_xh[sidx] = hi;
                g_xl[sidx] = lo;
            } else if (t == TLEN - 1) {
                g_hA[b * H + c] = hn;
            }
        }
        __syncthreads();
        xv = xn;
    }
}

// ---------------------------------------------------------------------------
// Persistent GRU layer 1 (H=256), 4-CTA cluster, 192 threads/CTA, NB=2.
// 64 clusters (256 CTAs) -> 2 INDEPENDENT clusters co-resident per SM:
// while one cluster stalls at its per-step barrier.cluster, the other's
// warps keep the FMA pipe busy. Each thread owns the FULL k=256 of one
// gate column (UR=120 regs + KT=136 smem) -> no cross-k reduction.
// ---------------------------------------------------------------------------
__global__ void __cluster_dims__(4, 1, 1) __launch_bounds__(192, 2)
gru_layer1_kernel(const float* __restrict__ U,
                  const float* __restrict__ brec)
{
    constexpr int H = 256, NC3 = 768;
    constexpr int NB = 2;              // batches per cluster
    constexpr int UR = 120;            // k in registers per thread
    constexpr int KT = 136;            // k tail in smem per thread (KT%4==0)

    extern __shared__ float smem[];
    float* hsb  = smem;                 // [2][NB][256] = 1024 floats (16B-aligned)
    float* Ut   = hsb + 1024;           // [KT/4][192][4] = 26112 floats
    float* pres = Ut + (KT / 4) * 192 * 4;   // [192][NB] = 384
    float* xsm  = pres + 192 * NB;      // [192][NB] = 384

    const int t = threadIdx.x;          // 0..191 == gate column c
    const int c = t;
    uint32_t rank;
    asm("mov.u32 %0, %%cluster_ctarank;" : "=r"(rank));
    const int bgrp = blockIdx.y;        // 0..63

    const int gg = c >> 6, il = c & 63;
    const int gc = gg * H + (int)rank * 64 + il;   // global gate column

    // U column: first UR k-values in packed-f32x2 registers.
    ull upk[UR / 2];
#pragma unroll
    for (int jp = 0; jp < UR / 2; jp++) {
        float f0 = U[(size_t)(2 * jp)     * NC3 + gc];
        float f1 = U[(size_t)(2 * jp + 1) * NC3 + gc];
        upk[jp] = packf2(f0, f1);
    }
    // Tail KT k-values in smem, [jq][t][4] conflict-free layout.
    for (int j = 0; j < KT; j++)
        Ut[((j >> 2) * 192 + t) * 4 + (j & 3)] = U[(size_t)(UR + j) * NC3 + gc];

    for (int idx = t; idx < 2 * NB * H; idx += 192) hsb[idx] = 0.0f;

    const float br = brec[gc];
    const uint32_t hsb_u32 = smem_u32(hsb);

    __syncthreads();
    CLUSTER_SYNC_ASM();                 // h zeros visible cluster-wide

    // prefetch xg for t=0
    float xv[NB];
#pragma unroll
    for (int bs = 0; bs < NB; bs++)
        xv[bs] = g_xg[((size_t)(bgrp * NB + bs) * TLEN + 0) * NC3 + gc];

    for (int step = 0; step < TLEN; step++) {
        const int cur = step & 1;
        const int nxt = cur ^ 1;
        const float* hc = hsb + cur * (NB * H);
        const int tn = (step + 1 < TLEN) ? step + 1 : step;

        float xn[NB];
#pragma unroll
        for (int bs = 0; bs < NB; bs++)
            xn[bs] = g_xg[((size_t)(bgrp * NB + bs) * TLEN + tn) * NC3 + gc];

        ull accA[NB], accB[NB];
#pragma unroll
        for (int bs = 0; bs < NB; bs++) { accA[bs] = 0ull; accB[bs] = 0ull; }

        // main: UR k-values from registers, h broadcast from smem
#pragma unroll
        for (int kq = 0; kq < UR / 4; kq++) {
#pragma unroll
            for (int bs = 0; bs < NB; bs++) {
                ulonglong2 hv = *(const ulonglong2*)&hc[bs * H + kq * 4];
                FMA_X2(accA[bs], upk[2 * kq],     hv.x);
                FMA_X2(accB[bs], upk[2 * kq + 1], hv.y);
            }
        }
        // tail: KT k-values from smem
#pragma unroll
        for (int jq = 0; jq < KT / 4; jq++) {
            ulonglong2 uv = *(const ulonglong2*)&Ut[(jq * 192 + t) * 4];
#pragma unroll
            for (int bs = 0; bs < NB; bs++) {
                ulonglong2 hv = *(const ulonglong2*)&hc[bs * H + UR + jq * 4];
                FMA_X2(accA[bs], uv.x, hv.x);
                FMA_X2(accB[bs], uv.y, hv.y);
            }
        }

        float2 ps;
        ps.x = sumf2(accA[0]) + sumf2(accB[0]) + br;
        ps.y = sumf2(accA[1]) + sumf2(accB[1]) + br;
        *(float2*)&pres[c * NB] = ps;
        *(float2*)&xsm[c * NB]  = make_float2(xv[0], xv[1]);
        __syncthreads();

        // gate combine + DSMEM broadcast: items (bs, j) over threads < 128
        if (t < NB * 64) {
            const int bs = t >> 6, j = t & 63;
            const int jz = j, jr = 64 + j, jh = 128 + j;
            float z = sigf(xsm[jz * NB + bs] + pres[jz * NB + bs]);
            float r = sigf(xsm[jr * NB + bs] + pres[jr * NB + bs]);
            float cand = xsm[jh * NB + bs] + r * pres[jh * NB + bs];
            float hh = sigf(cand);
            float hold = hc[bs * H + (int)rank * 64 + j];
            float hn = z * hold + (1.0f - z) * hh;

            int b = bgrp * NB + bs;
            size_t sidx = ((size_t)b * TLEN + step) * H + rank * 64 + j;
            __nv_bfloat16 hi, lo;
            bf16_split(hn, hi, lo);
            g_xh[sidx] = hi;
            g_xl[sidx] = lo;

            uint32_t dst = hsb_u32 +
                (uint32_t)((nxt * (NB * H) + bs * H + (int)rank * 64 + j) * 4);
#pragma unroll
            for (uint32_t rr = 0; rr < 4; rr++) st_cluster_f32(dst, rr, hn);
        }
        CLUSTER_SYNC_ASM();

#pragma unroll
        for (int bs = 0; bs < NB; bs++) xv[bs] = xn[bs];
    }
}

// ---------------------------------------------------------------------------
// Output head: out[b] = sigmoid(h3[b,:] . Wo + bo)
// ---------------------------------------------------------------------------
__global__ void head_kernel(const float* __restrict__ Wo,
                            const float* __restrict__ bo,
                            float* __restrict__ out)
{
    int b = threadIdx.x;
    if (b < BSZ) {
        float s = bo[0];
#pragma unroll
        for (int k = 0; k < 64; k++) s += g_hA[b * 64 + k] * Wo[k];
        out[b] = sigf(s);
    }
}

// ---------------------------------------------------------------------------
// kernel_launch. Inputs: text, W1, U1, b1, W2, U2, b2, W3, U3, b3, Wo, bo
// Launch order keeps gru_layer1_kernel 4th so ncu profiles it.
// ---------------------------------------------------------------------------
extern "C" void kernel_launch(void* const* d_in, const int* in_sizes, int n_in,
                              void* d_out, int out_size)
{
    (void)in_sizes; (void)n_in; (void)out_size;

    const float* text = (const float*)d_in[0];
    const float* W1   = (const float*)d_in[1];
    const float* U1   = (const float*)d_in[2];
    const float* b1   = (const float*)d_in[3];
    const float* W2   = (const float*)d_in[4];
    const float* U2   = (const float*)d_in[5];
    const float* b2   = (const float*)d_in[6];
    const float* W3   = (const float*)d_in[7];
    const float* U3   = (const float*)d_in[8];
    const float* b3   = (const float*)d_in[9];
    const float* Wo   = (const float*)d_in[10];
    const float* bo   = (const float*)d_in[11];
    float* out = (float*)d_out;

    const int M = BSZ * TLEN;                 // 65536

    // Dynamic smem (bytes)
    // layer1: 1024 + 34*192*4 + 384 + 384 = 27904 floats = 111616 B per CTA
    const size_t smem_l1 = (size_t)(1024 + (136 / 4) * 192 * 4 + 384 + 384) * 4;
    const size_t smem_l2 = (size_t)(384 * 36 + 128 + 384 + 384) * 4;
    const size_t smem_l3 = (size_t)(64 + 192 + 192) * 4;

    cudaFuncSetAttribute(gru_layer1_kernel,
                         cudaFuncAttributeMaxDynamicSharedMemorySize, (int)smem_l1);
    cudaFuncSetAttribute((const void*)gru_layer_reg_kernel<128, 96, false, true>,
                         cudaFuncAttributeMaxDynamicSharedMemorySize, (int)smem_l2);
    cudaFuncSetAttribute((const void*)gru_layer_reg_kernel<64, 64, true, false>,
                         cudaFuncAttributeMaxDynamicSharedMemorySize, (int)smem_l3);

    // ---- Layer 1: F=128 -> H=256 (gru_layer1 is the 4th launch for ncu) ----
    wsplit_kernel<<<(128 * 768 + 255) / 256, 256>>>(W1, 128, 768, 0);
    xsplit_kernel<<<(M * 128 + 255) / 256, 256>>>(text, M * 128);
    gemm_mma_kernel<<<dim3(768 / 64, M / 128), 256>>>(b1, 128, 768, 0);
    gru_layer1_kernel<<<dim3(4, 64), 192, smem_l1>>>(U1, b1 + 768);

    // ---- Layer 2: H=256 -> H=128 ----
    wsplit_kernel<<<(256 * 384 + 255) / 256, 256>>>(W2, 256, 384, 98304);
    gemm_mma_kernel<<<dim3(384 / 64, M / 128), 256>>>(b2, 256, 384, 98304);
    gru_layer_reg_kernel<128, 96, false, true><<<BSZ, 384, smem_l2>>>(U2, b2 + 384);

    // ---- Layer 3: H=128 -> H=64 ----
    wsplit_kernel<<<(128 * 192 + 255) / 256, 256>>>(W3, 128, 192, 196608);
    gemm_mma_kernel<<<dim3(192 / 64, M / 128), 256>>>(b3, 128, 192, 196608);
    gru_layer_reg_kernel<64, 64, true, false><<<BSZ, 192, smem_l3>>>(U3, b3 + 192);

    // ---- Head ----
    head_kernel<<<1, 128>>>(Wo, bo, out);
}

// round 17
// speedup vs baseline: 1.2080x; 1.1139x over previous
#include <cuda_runtime.h>
#include <cuda_bf16.h>
#include <math.h>
#include <stdint.h>

// Problem constants
#define BSZ  128
#define TLEN 512
// H1=256, H2=128, H3=64

// ---------------------------------------------------------------------------
// Static device scratch (no runtime allocation).
// ---------------------------------------------------------------------------
__device__ float         g_xg[(size_t)BSZ * TLEN * 768];
__device__ __nv_bfloat16 g_xh[(size_t)BSZ * TLEN * 256];
__device__ __nv_bfloat16 g_xl[(size_t)BSZ * TLEN * 256];
__device__ __nv_bfloat16 g_wth[221184];
__device__ __nv_bfloat16 g_wtl[221184];
__device__ float         g_hA[BSZ * 64];

typedef unsigned long long ull;

__device__ __forceinline__ float sigf(float x) {
    return __fdividef(1.0f, 1.0f + __expf(-x));
}

__device__ __forceinline__ uint32_t smem_u32(const void* p) {
    uint32_t a;
    asm("{ .reg .u64 t; cvta.to.shared.u64 t, %1; cvt.u32.u64 %0, t; }"
        : "=r"(a) : "l"(p));
    return a;
}

__device__ __forceinline__ void st_cluster_f32(uint32_t laddr, uint32_t rank, float v) {
    uint32_t r;
    asm volatile("mapa.shared::cluster.u32 %0, %1, %2;" : "=r"(r) : "r"(laddr), "r"(rank));
    asm volatile("st.shared::cluster.b32 [%0], %1;" :: "r"(r), "r"(__float_as_uint(v)) : "memory");
}

#define CLUSTER_SYNC_ASM() do {                                          \
    asm volatile("barrier.cluster.arrive.aligned;" ::: "memory");        \
    asm volatile("barrier.cluster.wait.aligned;"   ::: "memory");        \
} while (0)

// cp.async 16-byte global->shared copy (sm_80 baseline PTX)
#define CP_ASYNC16(smem_addr, gptr) \
    asm volatile("cp.async.ca.shared.global [%0], [%1], 16;" \
        :: "r"((uint32_t)(smem_addr)), "l"(gptr) : "memory")
#define CP_ASYNC_COMMIT() asm volatile("cp.async.commit_group;" ::: "memory")
#define CP_ASYNC_WAIT(n)  asm volatile("cp.async.wait_group %0;" :: "n"(n) : "memory")

// Packed dual-fp32 FMA (Blackwell f32x2 pipe): acc += a * b elementwise.
#define FMA_X2(acc, a, b) \
    asm("fma.rn.f32x2 %0, %1, %2, %0;" : "+l"(acc) : "l"(a), "l"(b))

__device__ __forceinline__ ull packf2(float lo, float hi) {
    return (ull)__float_as_uint(lo) | ((ull)__float_as_uint(hi) << 32);
}
__device__ __forceinline__ float sumf2(ull v) {
    return __uint_as_float((uint32_t)v) + __uint_as_float((uint32_t)(v >> 32));
}

// bf16 hi/lo split of an fp32 value
__device__ __forceinline__ void bf16_split(float a, __nv_bfloat16& hi, __nv_bfloat16& lo) {
    hi = __float2bfloat16_rn(a);
    lo = __float2bfloat16_rn(a - __bfloat162float(hi));
}

// m16n8k16 bf16 MMA, fp32 accumulate
#define MMA_BF16(c, a, b)                                                       \
    asm volatile(                                                               \
        "mma.sync.aligned.m16n8k16.row.col.f32.bf16.bf16.f32 "                  \
        "{%0,%1,%2,%3}, {%4,%5,%6,%7}, {%8,%9}, {%0,%1,%2,%3};"                 \
        : "+f"((c)[0]), "+f"((c)[1]), "+f"((c)[2]), "+f"((c)[3])                \
        : "r"((a)[0]), "r"((a)[1]), "r"((a)[2]), "r"((a)[3]),                   \
          "r"((b)[0]), "r"((b)[1]))

// ---------------------------------------------------------------------------
// Weight transpose + bf16 hi/lo split:  W [K,N] fp32 -> WT_hi/WT_lo [N,K] bf16
// ---------------------------------------------------------------------------
__global__ void wsplit_kernel(const float* __restrict__ W, int K, int N, int off)
{
    int idx = blockIdx.x * 256 + threadIdx.x;
    if (idx < K * N) {
        int k = idx / N, n = idx % N;
        __nv_bfloat16 hi, lo;
        bf16_split(W[idx], hi, lo);
        g_wth[off + (size_t)n * K + k] = hi;
        g_wtl[off + (size_t)n * K + k] = lo;
    }
}

// ---------------------------------------------------------------------------
// X split: fp32 [n] -> g_xh/g_xl bf16 (used once, for `text`)
// ---------------------------------------------------------------------------
__global__ void xsplit_kernel(const float* __restrict__ X, int n)
{
    int idx = blockIdx.x * 256 + threadIdx.x;
    if (idx < n) {
        __nv_bfloat16 hi, lo;
        bf16_split(X[idx], hi, lo);
        g_xh[idx] = hi;
        g_xl[idx] = lo;
    }
}

// ---------------------------------------------------------------------------
// bf16x3 tensor-core GEMM with bias, 2-stage cp.async double buffering.
//   A hi/lo: g_xh/g_xl [M,K] row-major bf16
//   WT hi/lo: g_wth/g_wtl + wt_off, [Ntot,K] row-major bf16 (B col-major)
// CTA tile 128(M) x 64(N), 8 warps 4x2 (32x32 each), BK=32.
// Dynamic smem: 2 stages x (Ah,Al[128x40] + Bh,Bl[64x40]) bf16.
// ---------------------------------------------------------------------------
#define GSTG (128 * 40 + 128 * 40 + 64 * 40 + 64 * 40)   // bf16 per stage = 15360

__global__ void __launch_bounds__(256, 2)
gemm_mma_kernel(const float* __restrict__ bias, int K, int Ntot, int wt_off)
{
    extern __shared__ __nv_bfloat16 smem_g[];

    const int tid  = threadIdx.x;
    const int wid  = tid >> 5;
    const int lane = tid & 31;
    const int wm   = wid & 3;
    const int wn   = wid >> 2;
    const int m0   = blockIdx.y * 128;
    const int n0   = blockIdx.x * 64;
    const int g    = lane >> 2;
    const int tg   = lane & 3;

    const __nv_bfloat16* wth = g_wth + wt_off;
    const __nv_bfloat16* wtl = g_wtl + wt_off;

    // per-thread load coordinates
    const int ar = tid >> 1;              // A row 0..127 (2 threads/row)
    const int aq = (tid & 1) * 2;         // A quad pair: quads {0,1} or {2,3}
    const int brr = tid >> 2;             // B row 0..63
    const int bq  = tid & 3;              // B quad 0..3

    // stage pointers
    __nv_bfloat16* Ah[2]; __nv_bfloat16* Al[2];
    __nv_bfloat16* Bh[2]; __nv_bfloat16* Bl[2];
#pragma unroll
    for (int s = 0; s < 2; s++) {
        __nv_bfloat16* base = smem_g + s * GSTG;
        Ah[s] = base;
        Al[s] = base + 128 * 40;
        Bh[s] = base + 2 * 128 * 40;
        Bl[s] = base + 2 * 128 * 40 + 64 * 40;
    }

    const int nk = K / 32;

    // issue loads for chunk kc into stage s
    auto issue = [&](int kc, int s) {
        const int k0 = kc * 32;
        // A: rows 0..127, each thread copies 2x16B for Ah and Al
        size_t goA = (size_t)(m0 + ar) * K + k0 + aq * 8;
        CP_ASYNC16(smem_u32(&Ah[s][ar * 40 + aq * 8]),     &g_xh[goA]);
        CP_ASYNC16(smem_u32(&Ah[s][ar * 40 + (aq + 1) * 8]), &g_xh[goA + 8]);
        CP_ASYNC16(smem_u32(&Al[s][ar * 40 + aq * 8]),     &g_xl[goA]);
        CP_ASYNC16(smem_u32(&Al[s][ar * 40 + (aq + 1) * 8]), &g_xl[goA + 8]);
        // B: rows 0..63, 1x16B each for Bh and Bl
        size_t goB = (size_t)(n0 + brr) * K + k0 + bq * 8;
        CP_ASYNC16(smem_u32(&Bh[s][brr * 40 + bq * 8]), &wth[goB]);
        CP_ASYNC16(smem_u32(&Bl[s][brr * 40 + bq * 8]), &wtl[goB]);
    };

    float c[2][4][4];
#pragma unroll
    for (int mt = 0; mt < 2; mt++)
#pragma unroll
        for (int nt = 0; nt < 4; nt++)
#pragma unroll
            for (int i = 0; i < 4; i++) c[mt][nt][i] = 0.0f;

    issue(0, 0);
    CP_ASYNC_COMMIT();

    for (int kc = 0; kc < nk; kc++) {
        const int s = kc & 1;
        if (kc + 1 < nk) {
            issue(kc + 1, s ^ 1);
            CP_ASYNC_COMMIT();
            CP_ASYNC_WAIT(1);           // stage s complete
        } else {
            CP_ASYNC_WAIT(0);
        }
        __syncthreads();

#pragma unroll
        for (int ks = 0; ks < 2; ks++) {
            uint32_t ah[2][4], al[2][4], bh[4][2], bl[4][2];
            const int cb = ks * 16 + tg * 2;
#pragma unroll
            for (int mt = 0; mt < 2; mt++) {
                int r0 = wm * 32 + mt * 16 + g;
                ah[mt][0] = *(const uint32_t*)&Ah[s][(r0    ) * 40 + cb];
                ah[mt][1] = *(const uint32_t*)&Ah[s][(r0 + 8) * 40 + cb];
                ah[mt][2] = *(const uint32_t*)&Ah[s][(r0    ) * 40 + cb + 8];
                ah[mt][3] = *(const uint32_t*)&Ah[s][(r0 + 8) * 40 + cb + 8];
                al[mt][0] = *(const uint32_t*)&Al[s][(r0    ) * 40 + cb];
                al[mt][1] = *(const uint32_t*)&Al[s][(r0 + 8) * 40 + cb];
                al[mt][2] = *(const uint32_t*)&Al[s][(r0    ) * 40 + cb + 8];
                al[mt][3] = *(const uint32_t*)&Al[s][(r0 + 8) * 40 + cb + 8];
            }
#pragma unroll
            for (int nt = 0; nt < 4; nt++) {
                int rn = wn * 32 + nt * 8 + g;
                bh[nt][0] = *(const uint32_t*)&Bh[s][rn * 40 + cb];
                bh[nt][1] = *(const uint32_t*)&Bh[s][rn * 40 + cb + 8];
                bl[nt][0] = *(const uint32_t*)&Bl[s][rn * 40 + cb];
                bl[nt][1] = *(const uint32_t*)&Bl[s][rn * 40 + cb + 8];
            }
#pragma unroll
            for (int mt = 0; mt < 2; mt++)
#pragma unroll
                for (int nt = 0; nt < 4; nt++) {
                    MMA_BF16(c[mt][nt], ah[mt], bh[nt]);
                    MMA_BF16(c[mt][nt], ah[mt], bl[nt]);
                    MMA_BF16(c[mt][nt], al[mt], bh[nt]);
                }
        }
        __syncthreads();                 // stage s free for reuse at kc+2
    }

#pragma unroll
    for (int mt = 0; mt < 2; mt++)
#pragma unroll
        for (int nt = 0; nt < 4; nt++) {
            int row = m0 + wm * 32 + mt * 16 + g;
            int col = n0 + wn * 32 + nt * 8 + tg * 2;
            float b0 = bias[col], b1 = bias[col + 1];
            float2 o0 = make_float2(c[mt][nt][0] + b0, c[mt][nt][1] + b1);
            float2 o1 = make_float2(c[mt][nt][2] + b0, c[mt][nt][3] + b1);
            *(float2*)&g_xg[(size_t)row * Ntot + col]       = o0;
            *(float2*)&g_xg[(size_t)(row + 8) * Ntot + col] = o1;
        }
}

// ---------------------------------------------------------------------------
// Persistent GRU layers 2/3: U register-cached + packed f32x2 FMA (R11 exact).
// ---------------------------------------------------------------------------
template <int H, int UREG, bool RELU, bool WSEQ>
__global__ void __launch_bounds__(3 * H, 1)
gru_layer_reg_kernel(const float* __restrict__ U,
                     const float* __restrict__ brec)
{
    constexpr int NC  = 3 * H;
    constexpr int KS  = H - UREG;
    constexpr int KSp = (KS > 0) ? KS + 4 : 4;

    extern __shared__ float smem[];
    float* UsT  = smem;
    float* hs   = UsT + (KS > 0 ? NC * KSp : 0);
    float* pres = hs + H;
    float* xsm  = pres + NC;

    const int b = blockIdx.x;
    const int c = threadIdx.x;

    ull upk[UREG / 2];
#pragma unroll
    for (int jp = 0; jp < UREG / 2; jp++) {
        float f0 = U[(size_t)(2 * jp)     * NC + c];
        float f1 = U[(size_t)(2 * jp + 1) * NC + c];
        upk[jp] = packf2(f0, f1);
    }
    if constexpr (KS > 0) {
        for (int k = 0; k < KS; k++)
            UsT[c * KSp + k] = U[(size_t)(UREG + k) * NC + c];
    }

    if (c < H) hs[c] = 0.0f;
    const float br = brec[c];
    __syncthreads();

    const float* xgb = &g_xg[(size_t)b * TLEN * NC + c];

    float xv = xgb[0];
    for (int t = 0; t < TLEN; t++) {
        float xn = xgb[(size_t)(t + 1 < TLEN ? t + 1 : t) * NC];

        ull accA = 0ull, accB = 0ull;
#pragma unroll
        for (int kq = 0; kq < UREG / 4; kq++) {
            ulonglong2 hv = *(const ulonglong2*)&hs[kq * 4];
            FMA_X2(accA, upk[2 * kq],     hv.x);
            FMA_X2(accB, upk[2 * kq + 1], hv.y);
        }
        if constexpr (KS > 0) {
#pragma unroll
            for (int jq = 0; jq < KS / 4; jq++) {
                ulonglong2 uv = *(const ulonglong2*)&UsT[c * KSp + jq * 4];
                ulonglong2 hv = *(const ulonglong2*)&hs[UREG + jq * 4];
                FMA_X2(accA, uv.x, hv.x);
                FMA_X2(accB, uv.y, hv.y);
            }
        }
        pres[c] = sumf2(accA) + sumf2(accB) + br;
        xsm[c]  = xv;
        __syncthreads();

        if (c < H) {
            float z = sigf(xsm[c] + pres[c]);
            float r = sigf(xsm[H + c] + pres[H + c]);
            float cand = xsm[2 * H + c] + r * pres[2 * H + c];
            float hh = RELU ? fmaxf(cand, 0.0f) : sigf(cand);
            float hn = z * hs[c] + (1.0f - z) * hh;
            hs[c] = hn;
            if (WSEQ) {
                size_t sidx = ((size_t)b * TLEN + t) * H + c;
                __nv_bfloat16 hi, lo;
                bf16_split(hn, hi, lo);
                g_xh[sidx] = hi;
                g_xl[sidx] = lo;
            } else if (t == TLEN - 1) {
                g_hA[b * H + c] = hn;
            }
        }
        __syncthreads();
        xv = xn;
    }
}

// ---------------------------------------------------------------------------
// Persistent GRU layer 1 (H=256), 4-CTA cluster, 384 threads/CTA (R11 exact).
// ---------------------------------------------------------------------------
__global__ void __cluster_dims__(4, 1, 1) __launch_bounds__(384, 1)
gru_layer1_kernel(const float* __restrict__ U,
                  const float* __restrict__ brec)
{
    constexpr int H = 256, NC3 = 768;
    constexpr int NB = 4;              // batches per cluster
    constexpr int UR = 96;             // k in registers per thread
    constexpr int KT = 32;             // k tail in smem per thread

    extern __shared__ float smem[];
    float* hsb  = smem;                 // [2][NB][256] double-buffered h (2048)
    float* Ut   = hsb + 2048;           // [8][384][4] U tail (12288)
    float* part = Ut + 12288;           // [2][192][4] partial sums (1536)
    float* xsm  = part + 1536;          // [192][4] xg staging (768)

    const int t    = threadIdx.x;
    const int half = (t >= 192) ? 1 : 0;      // warps 0-5 / 6-11
    const int c    = t - half * 192;
    uint32_t rank;
    asm("mov.u32 %0, %%cluster_ctarank;" : "=r"(rank));
    const int bgrp = blockIdx.y;

    const int gg = c >> 6, il = c & 63;
    const int gc = gg * H + (int)rank * 64 + il;   // global gate column
    const int kbase = half * 128;

    ull upk[UR / 2];
#pragma unroll
    for (int jp = 0; jp < UR / 2; jp++) {
        float f0 = U[(size_t)(kbase + 2 * jp)     * NC3 + gc];
        float f1 = U[(size_t)(kbase + 2 * jp + 1) * NC3 + gc];
        upk[jp] = packf2(f0, f1);
    }
    for (int j = 0; j < KT; j++)
        Ut[((j >> 2) * 384 + t) * 4 + (j & 3)] = U[(size_t)(kbase + UR + j) * NC3 + gc];

    for (int idx = t; idx < 2 * NB * H; idx += 384) hsb[idx] = 0.0f;

    const float br = brec[gc];
    const uint32_t hsb_u32 = smem_u32(hsb);

    __syncthreads();
    CLUSTER_SYNC_ASM();

    float xv[NB];
    if (half == 0) {
#pragma unroll
        for (int bs = 0; bs < NB; bs++)
            xv[bs] = g_xg[((size_t)(bgrp * NB + bs) * TLEN + 0) * NC3 + gc];
    }

    for (int step = 0; step < TLEN; step++) {
        const int cur = step & 1;
        const int nxt = cur ^ 1;
        const float* hc = hsb + cur * (NB * H);
        const int tn = (step + 1 < TLEN) ? step + 1 : step;

        float xn[NB];
        if (half == 0) {
#pragma unroll
            for (int bs = 0; bs < NB; bs++)
                xn[bs] = g_xg[((size_t)(bgrp * NB + bs) * TLEN + tn) * NC3 + gc];
        }

        ull accA[NB], accB[NB];
#pragma unroll
        for (int bs = 0; bs < NB; bs++) { accA[bs] = 0ull; accB[bs] = 0ull; }

#pragma unroll
        for (int kq = 0; kq < UR / 4; kq++) {
#pragma unroll
            for (int bs = 0; bs < NB; bs++) {
                ulonglong2 hv = *(const ulonglong2*)&hc[bs * H + kbase + kq * 4];
                FMA_X2(accA[bs], upk[2 * kq],     hv.x);
                FMA_X2(accB[bs], upk[2 * kq + 1], hv.y);
            }
        }
#pragma unroll
        for (int jq = 0; jq < KT / 4; jq++) {
            ulonglong2 uv = *(const ulonglong2*)&Ut[(jq * 384 + t) * 4];
#pragma unroll
            for (int bs = 0; bs < NB; bs++) {
                ulonglong2 hv = *(const ulonglong2*)&hc[bs * H + kbase + UR + jq * 4];
                FMA_X2(accA[bs], uv.x, hv.x);
                FMA_X2(accB[bs], uv.y, hv.y);
            }
        }

        float4 ps;
        ps.x = sumf2(accA[0]) + sumf2(accB[0]);
        ps.y = sumf2(accA[1]) + sumf2(accB[1]);
        ps.z = sumf2(accA[2]) + sumf2(accB[2]);
        ps.w = sumf2(accA[3]) + sumf2(accB[3]);
        if (half == 0) {
            ps.x += br; ps.y += br; ps.z += br; ps.w += br;
            *(float4*)&xsm[c * 4] = make_float4(xv[0], xv[1], xv[2], xv[3]);
        }
        *(float4*)&part[(half * 192 + c) * 4] = ps;
        __syncthreads();

        const int nxt2 = nxt;
#pragma unroll
        for (int item = t; item < NB * 64; item += 384) {
            int bs = item >> 6, j = item & 63;
            float z = sigf(xsm[(j) * 4 + bs]        + part[(j) * 4 + bs]        + part[(192 + j) * 4 + bs]);
            float r = sigf(xsm[(64 + j) * 4 + bs]   + part[(64 + j) * 4 + bs]   + part[(192 + 64 + j) * 4 + bs]);
            float ph =      part[(128 + j) * 4 + bs] + part[(192 + 128 + j) * 4 + bs];
            float cand = xsm[(128 + j) * 4 + bs] + r * ph;
            float hh = sigf(cand);
            float hold = hc[bs * H + (int)rank * 64 + j];
            float hn = z * hold + (1.0f - z) * hh;

            int b = bgrp * NB + bs;
            size_t sidx = ((size_t)b * TLEN + step) * H + rank * 64 + j;
            __nv_bfloat16 hi, lo;
            bf16_split(hn, hi, lo);
            g_xh[sidx] = hi;
            g_xl[sidx] = lo;

            uint32_t dst = hsb_u32 +
                (uint32_t)((nxt2 * (NB * H) + bs * H + (int)rank * 64 + j) * 4);
#pragma unroll
            for (uint32_t rr = 0; rr < 4; rr++) st_cluster_f32(dst, rr, hn);
        }
        CLUSTER_SYNC_ASM();

        if (half == 0) {
#pragma unroll
            for (int bs = 0; bs < NB; bs++) xv[bs] = xn[bs];
        }
    }
}

// ---------------------------------------------------------------------------
// Output head: out[b] = sigmoid(h3[b,:] . Wo + bo)
// ---------------------------------------------------------------------------
__global__ void head_kernel(const float* __restrict__ Wo,
                            const float* __restrict__ bo,
                            float* __restrict__ out)
{
    int b = threadIdx.x;
    if (b < BSZ) {
        float s = bo[0];
#pragma unroll
        for (int k = 0; k < 64; k++) s += g_hA[b * 64 + k] * Wo[k];
        out[b] = sigf(s);
    }
}

// ---------------------------------------------------------------------------
// kernel_launch. Inputs: text, W1, U1, b1, W2, U2, b2, W3, U3, b3, Wo, bo
// Launch order puts gemm_mma_kernel (layer 1) 4th so ncu profiles the GEMM.
// ---------------------------------------------------------------------------
extern "C" void kernel_launch(void* const* d_in, const int* in_sizes, int n_in,
                              void* d_out, int out_size)
{
    (void)in_sizes; (void)n_in; (void)out_size;

    const float* text = (const float*)d_in[0];
    const float* W1   = (const float*)d_in[1];
    const float* U1   = (const float*)d_in[2];
    const float* b1   = (const float*)d_in[3];
    const float* W2   = (const float*)d_in[4];
    const float* U2   = (const float*)d_in[5];
    const float* b2   = (const float*)d_in[6];
    const float* W3   = (const float*)d_in[7];
    const float* U3   = (const float*)d_in[8];
    const float* b3   = (const float*)d_in[9];
    const float* Wo   = (const float*)d_in[10];
    const float* bo   = (const float*)d_in[11];
    float* out = (float*)d_out;

    const int M = BSZ * TLEN;                 // 65536

    // Dynamic smem (bytes)
    const size_t smem_gemm = (size_t)(2 * GSTG) * sizeof(__nv_bfloat16); // 61440
    const size_t smem_l1 = (size_t)(2048 + 12288 + 1536 + 768) * 4;      // 66560
    const size_t smem_l2 = (size_t)(384 * 36 + 128 + 384 + 384) * 4;
    const size_t smem_l3 = (size_t)(64 + 192 + 192) * 4;

    cudaFuncSetAttribute(gemm_mma_kernel,
                         cudaFuncAttributeMaxDynamicSharedMemorySize, (int)smem_gemm);
    cudaFuncSetAttribute(gru_layer1_kernel,
                         cudaFuncAttributeMaxDynamicSharedMemorySize, (int)smem_l1);
    cudaFuncSetAttribute((const void*)gru_layer_reg_kernel<128, 96, false, true>,
                         cudaFuncAttributeMaxDynamicSharedMemorySize, (int)smem_l2);
    cudaFuncSetAttribute((const void*)gru_layer_reg_kernel<64, 64, true, false>,
                         cudaFuncAttributeMaxDynamicSharedMemorySize, (int)smem_l3);

    // ---- Prep: weight splits + text split (gemm1 is the 4th launch) ----
    wsplit_kernel<<<(128 * 768 + 255) / 256, 256>>>(W1, 128, 768, 0);
    xsplit_kernel<<<(M * 128 + 255) / 256, 256>>>(text, M * 128);
    wsplit_kernel<<<(256 * 384 + 255) / 256, 256>>>(W2, 256, 384, 98304);

    // ---- Layer 1: F=128 -> H=256 ----
    gemm_mma_kernel<<<dim3(768 / 64, M / 128), 256, smem_gemm>>>(b1, 128, 768, 0);
    gru_layer1_kernel<<<dim3(4, 32), 384, smem_l1>>>(U1, b1 + 768);

    // ---- Layer 2: H=256 -> H=128 ----
    gemm_mma_kernel<<<dim3(384 / 64, M / 128), 256, smem_gemm>>>(b2, 256, 384, 98304);
    gru_layer_reg_kernel<128, 96, false, true><<<BSZ, 384, smem_l2>>>(U2, b2 + 384);

    // ---- Layer 3: H=128 -> H=64 ----
    wsplit_kernel<<<(128 * 192 + 255) / 256, 256>>>(W3, 128, 192, 196608);
    gemm_mma_kernel<<<dim3(192 / 64, M / 128), 256, smem_gemm>>>(b3, 128, 192, 196608);
    gru_layer_reg_kernel<64, 64, true, false><<<BSZ, 192, smem_l3>>>(U3, b3 + 192);

    // ---- Head ----
    head_kernel<<<1, 128>>>(Wo, bo, out);
}